// round 5
// baseline (speedup 1.0000x reference)
#include <cuda_runtime.h>
#include <math.h>

// ---------------------------------------------------------------------------
// Problem constants
// ---------------------------------------------------------------------------
#define B_   64
#define S_   512
#define F_   128
#define U_   512
#define SIGDIM 16512            // F + F*F
#define NB_  8                  // GRID_SIZE + SPLINE_ORDER
#define LN_EPS 1e-3f

// ---------------------------------------------------------------------------
// Device scratch (no cudaMalloc allowed)
// ---------------------------------------------------------------------------
__device__ float g_sig  [B_ * SIGDIM];      // [64][16512]  s1 | vec(s2)
__device__ float g_z1   [B_ * U_];          // sig@w1+b1
__device__ float g_yskip[B_ * U_];          // sig@ws+bs
__device__ float g_h2   [B_ * U_];          // elu(z1)@w2+b2
__device__ float g_g3   [B_ * U_];          // h2@w3+b3
__device__ float g_g4   [B_ * U_];          // h2@w4+b4
__device__ float g_y    [B_ * U_];          // yskip + glu
__device__ float g_attn [B_ * U_];          // softmax(LN(y))
__device__ float g_PQ   [B_ * 1152];        // [64][128 P | 1024 Q]
__device__ float g_Wc   [1152 * U_];        // [k][u] combined base+spline weight
__device__ float g_cur  [B_ * U_];          // PQ @ Wc (pre mean-scale)
__device__ float g_comb [B_ * 2 * U_];      // [current/S , h_prev]
__device__ float g_gates[4 * B_ * U_];      // f,i,c,o pre-activation

// ---------------------------------------------------------------------------
// Helpers
// ---------------------------------------------------------------------------
__device__ __forceinline__ float sigmoidf_(float x) { return 1.0f / (1.0f + expf(-x)); }

__device__ __forceinline__ float blockReduceSum(float v, float* smem) {
    int lane = threadIdx.x & 31, w = threadIdx.x >> 5;
    #pragma unroll
    for (int o = 16; o > 0; o >>= 1) v += __shfl_xor_sync(0xffffffffu, v, o);
    if (lane == 0) smem[w] = v;
    __syncthreads();
    int nw = blockDim.x >> 5;
    float r = (threadIdx.x < nw) ? smem[threadIdx.x] : 0.0f;
    if (w == 0) {
        #pragma unroll
        for (int o = 16; o > 0; o >>= 1) r += __shfl_xor_sync(0xffffffffu, r, o);
        if (lane == 0) smem[0] = r;
    }
    __syncthreads();
    float out = smem[0];
    __syncthreads();
    return out;
}

__device__ __forceinline__ float blockReduceMax(float v, float* smem) {
    int lane = threadIdx.x & 31, w = threadIdx.x >> 5;
    #pragma unroll
    for (int o = 16; o > 0; o >>= 1) v = fmaxf(v, __shfl_xor_sync(0xffffffffu, v, o));
    if (lane == 0) smem[w] = v;
    __syncthreads();
    int nw = blockDim.x >> 5;
    float r = (threadIdx.x < nw) ? smem[threadIdx.x] : -INFINITY;
    if (w == 0) {
        #pragma unroll
        for (int o = 16; o > 0; o >>= 1) r = fmaxf(r, __shfl_xor_sync(0xffffffffu, r, o));
        if (lane == 0) smem[0] = r;
    }
    __syncthreads();
    float out = smem[0];
    __syncthreads();
    return out;
}

// b-spline basis (grid_size=5, order=3): 8 basis values at x.
// grid[i] = -1 + 0.4*(i-3), i = 0..11  (matches reference exactly)
__device__ __forceinline__ void bspline8(float x, float* out) {
    float b[11];
    #pragma unroll
    for (int i = 0; i < 11; i++) {
        float gi  = -1.0f + 0.4f * (float)(i - 3);
        float gi1 = -1.0f + 0.4f * (float)(i - 2);
        b[i] = (x >= gi && x < gi1) ? 1.0f : 0.0f;
    }
    #pragma unroll
    for (int p = 1; p <= 3; p++) {
        float inv = 1.0f / (0.4f * (float)p);
        #pragma unroll
        for (int i = 0; i < 11 - 3; i++) {       // upper bound 8 covers all p (extra iters harmless? no!)
            // placeholder - replaced below
        }
        // proper bound loop:
        for (int i = 0; i < 11 - p; i++) {
            float gi    = -1.0f + 0.4f * (float)(i - 3);
            float gip1x = -1.0f + 0.4f * (float)(i + p + 1 - 3);
            b[i] = (x - gi) * inv * b[i] + (gip1x - x) * inv * b[i + 1];
        }
    }
    #pragma unroll
    for (int k = 0; k < 8; k++) out[k] = b[k];
}

// ---------------------------------------------------------------------------
// K1: init sig: s1 via telescoping, zero s2 region
// ---------------------------------------------------------------------------
__global__ void init_sig_kernel(const float* __restrict__ x, const float* __restrict__ tk) {
    int idx = blockIdx.x * blockDim.x + threadIdx.x;
    if (idx >= B_ * SIGDIM) return;
    int b = idx / SIGDIM, c = idx - b * SIGDIM;
    float v = 0.0f;
    if (c < F_) {
        v = tk[S_ - 1] * x[(b * S_ + (S_ - 1)) * F_ + c] - tk[0] * x[(b * S_) * F_ + c];
    }
    g_sig[idx] = v;
}

// ---------------------------------------------------------------------------
// K2: bias/zero init for all atomic-accumulated buffers
// layout: 9*32768 bias targets, then g_cur (32768) zeros, then g_PQ (73728) zeros
// ---------------------------------------------------------------------------
__global__ void init_small_kernel(const float* b1, const float* bsk, const float* b2,
                                  const float* b3, const float* b4,
                                  const float* bf, const float* bi,
                                  const float* bc, const float* bo) {
    int idx = blockIdx.x * blockDim.x + threadIdx.x;
    const int NBIAS = 9 * B_ * U_;                 // 294912
    if (idx < NBIAS) {
        int which = idx >> 15;       // /32768
        int r = idx & 32767;
        int u = r & (U_ - 1);
        float v; float* dst;
        switch (which) {
            case 0: dst = g_z1;            v = b1[u];  break;
            case 1: dst = g_yskip;         v = bsk[u]; break;
            case 2: dst = g_h2;            v = b2[u];  break;
            case 3: dst = g_g3;            v = b3[u];  break;
            case 4: dst = g_g4;            v = b4[u];  break;
            case 5: dst = g_gates;         v = bf[u];  break;
            case 6: dst = g_gates + 32768; v = bi[u];  break;
            case 7: dst = g_gates + 65536; v = bc[u];  break;
            default: dst = g_gates + 98304; v = bo[u]; break;
        }
        dst[r] = v;
    } else {
        int r = idx - NBIAS;
        if (r < B_ * U_)               g_cur[r] = 0.0f;
        else if (r < B_ * U_ + B_ * 1152) g_PQ[r - B_ * U_] = 0.0f;
    }
}

// ---------------------------------------------------------------------------
// K3: build combined weight Wc[k][u]: k<128 -> base_w[k][u]; else spline_w[u][f][kk]
// ---------------------------------------------------------------------------
__global__ void wc_transpose_kernel(const float* __restrict__ base_w,
                                    const float* __restrict__ spline_w) {
    int idx = blockIdx.x * blockDim.x + threadIdx.x;
    if (idx >= 1152 * U_) return;
    int k = idx / U_, u = idx - k * U_;
    float v;
    if (k < F_) v = base_w[k * U_ + u];
    else {
        int kk = k - F_;
        int f = kk >> 3, s = kk & 7;
        v = spline_w[(u * F_ + f) * NB_ + s];
    }
    g_Wc[idx] = v;
}

// ---------------------------------------------------------------------------
// K4: s2[b,i,j] = sum_t (0.5(w_t+w_{t+1})-w_0)_i * (w_{t+1}-w_t)_j
// batched GEMM, split-K over 4 chunks of 128 t-steps, atomicAdd into g_sig.
// block = 256 threads, each computes 8x8 of the 128x128 output.
// ---------------------------------------------------------------------------
__global__ void __launch_bounds__(256) sig2_kernel(const float* __restrict__ x,
                                                   const float* __restrict__ tk) {
    int b = blockIdx.y;
    int tBegin = blockIdx.x * 128;
    int tEnd = min(S_ - 1, tBegin + 128);          // dx indices 0..510

    __shared__ float a_s[32][128];
    __shared__ float d_s[32][128];
    __shared__ float w0_s[128];

    int tid = threadIdx.x;
    const float* xb = x + b * S_ * F_;
    if (tid < 128) w0_s[tid] = tk[0] * xb[tid];
    __syncthreads();

    int tx = tid & 15, ty = tid >> 4;
    float acc[8][8];
    #pragma unroll
    for (int i = 0; i < 8; i++)
        #pragma unroll
        for (int j = 0; j < 8; j++) acc[i][j] = 0.0f;

    for (int t0 = tBegin; t0 < tEnd; t0 += 32) {
        #pragma unroll
        for (int it = 0; it < 16; it++) {
            int e = tid + it * 256;                // 0..4095
            int kk = e >> 7, f = e & 127;
            int t = t0 + kk;
            float av = 0.0f, dv = 0.0f;
            if (t < tEnd) {
                float wt  = tk[t]     * xb[t * F_ + f];
                float wt1 = tk[t + 1] * xb[(t + 1) * F_ + f];
                dv = wt1 - wt;
                av = 0.5f * (wt + wt1) - w0_s[f];
            }
            a_s[kk][f] = av;
            d_s[kk][f] = dv;
        }
        __syncthreads();
        #pragma unroll 4
        for (int kk = 0; kk < 32; kk++) {
            float a8[8], d8[8];
            *(float4*)&a8[0] = *(const float4*)&a_s[kk][ty * 8];
            *(float4*)&a8[4] = *(const float4*)&a_s[kk][ty * 8 + 4];
            *(float4*)&d8[0] = *(const float4*)&d_s[kk][tx * 8];
            *(float4*)&d8[4] = *(const float4*)&d_s[kk][tx * 8 + 4];
            #pragma unroll
            for (int i = 0; i < 8; i++)
                #pragma unroll
                for (int j = 0; j < 8; j++) acc[i][j] = fmaf(a8[i], d8[j], acc[i][j]);
        }
        __syncthreads();
    }

    float* s2 = g_sig + b * SIGDIM + F_;
    #pragma unroll
    for (int i = 0; i < 8; i++)
        #pragma unroll
        for (int j = 0; j < 8; j++)
            atomicAdd(&s2[(ty * 8 + i) * F_ + tx * 8 + j], acc[i][j]);
}

// ---------------------------------------------------------------------------
// K5: generic split-K GEMM, M=64 fixed, N multiple of 128.
// C(64,N) += act(A)(64,K) @ B(K,N); atomicAdd epilogue.
// actA: 0 none, 1 elu
// ---------------------------------------------------------------------------
__global__ void __launch_bounds__(256) gemm64_acc(const float* __restrict__ A, int lda,
                                                  const float* __restrict__ Bw, int ldb,
                                                  float* __restrict__ C, int ldc,
                                                  int K, int kChunk, int actA) {
    int nTile = blockIdx.x;
    int kBegin = blockIdx.y * kChunk;
    int kEnd = min(K, kBegin + kChunk);

    __shared__ float As[16][68];       // padded, 16B-aligned rows
    __shared__ float Bs[16][128];

    int tid = threadIdx.x;
    int tx = tid & 15, ty = tid >> 4;
    int n0 = nTile * 128 + tx * 8;
    int m0 = ty * 4;

    float acc[4][8];
    #pragma unroll
    for (int i = 0; i < 4; i++)
        #pragma unroll
        for (int j = 0; j < 8; j++) acc[i][j] = 0.0f;

    for (int k0 = kBegin; k0 < kEnd; k0 += 16) {
        // A tile: 64 x 16
        #pragma unroll
        for (int it = 0; it < 4; it++) {
            int e = tid + it * 256;
            int m = e >> 4, kk = e & 15;
            int k = k0 + kk;
            float v = (k < kEnd) ? A[m * lda + k] : 0.0f;
            if (actA == 1) v = (v > 0.0f) ? v : (expf(v) - 1.0f);
            As[kk][m] = v;
        }
        // B tile: 16 x 128
        #pragma unroll
        for (int it = 0; it < 8; it++) {
            int e = tid + it * 256;
            int kk = e >> 7, n = e & 127;
            int k = k0 + kk;
            Bs[kk][n] = (k < kEnd) ? Bw[k * ldb + nTile * 128 + n] : 0.0f;
        }
        __syncthreads();
        #pragma unroll
        for (int kk = 0; kk < 16; kk++) {
            float a4[4], b8[8];
            *(float4*)&a4[0] = *(const float4*)&As[kk][m0];
            *(float4*)&b8[0] = *(const float4*)&Bs[kk][tx * 8];
            *(float4*)&b8[4] = *(const float4*)&Bs[kk][tx * 8 + 4];
            #pragma unroll
            for (int i = 0; i < 4; i++)
                #pragma unroll
                for (int j = 0; j < 8; j++) acc[i][j] = fmaf(a4[i], b8[j], acc[i][j]);
        }
        __syncthreads();
    }
    #pragma unroll
    for (int i = 0; i < 4; i++)
        #pragma unroll
        for (int j = 0; j < 8; j++)
            atomicAdd(&C[(m0 + i) * ldc + n0 + j], acc[i][j]);
}

// ---------------------------------------------------------------------------
// K6: y = yskip + sigmoid(g3) * g4
// ---------------------------------------------------------------------------
__global__ void glu_y_kernel() {
    int idx = blockIdx.x * blockDim.x + threadIdx.x;
    if (idx >= B_ * U_) return;
    g_y[idx] = g_yskip[idx] + sigmoidf_(g_g3[idx]) * g_g4[idx];
}

// ---------------------------------------------------------------------------
// K7: layernorm + softmax per batch row -> attn
// ---------------------------------------------------------------------------
__global__ void ln_softmax_kernel(const float* __restrict__ gamma,
                                  const float* __restrict__ beta) {
    __shared__ float red[32];
    int b = blockIdx.x, u = threadIdx.x;
    float v = g_y[b * U_ + u];
    float mu = blockReduceSum(v, red) * (1.0f / (float)U_);
    float d = v - mu;
    float var = blockReduceSum(d * d, red) * (1.0f / (float)U_);
    float yn = d * rsqrtf(var + LN_EPS) * gamma[u] + beta[u];
    float mx = blockReduceMax(yn, red);
    float e = expf(yn - mx);
    float s = blockReduceSum(e, red);
    g_attn[b * U_ + u] = e / s;
}

// ---------------------------------------------------------------------------
// K8: P[b,f] = sum_s attn[b,s]*silu(w), Q[b,f,k] = sum_s attn[b,s]*bspl_k(w)
// grid (B, 4 s-chunks), block 128 (one thread per f), atomicAdd into g_PQ.
// ---------------------------------------------------------------------------
__global__ void __launch_bounds__(128) pq_kernel(const float* __restrict__ x,
                                                 const float* __restrict__ tk) {
    int b = blockIdx.x, chunk = blockIdx.y;
    int f = threadIdx.x;
    int s0 = chunk * 128;

    __shared__ float att_s[128], tk_s[128];
    att_s[f] = g_attn[b * U_ + s0 + f];
    tk_s[f]  = tk[s0 + f];
    __syncthreads();

    float accP = 0.0f, accQ[8];
    #pragma unroll
    for (int k = 0; k < 8; k++) accQ[k] = 0.0f;

    const float* xb = x + (b * S_ + s0) * F_;
    for (int si = 0; si < 128; si++) {
        float att = att_s[si];
        float xw = tk_s[si] * xb[si * F_ + f];
        float sg = 1.0f / (1.0f + expf(-xw));
        accP = fmaf(att, xw * sg, accP);
        float bs[8];
        bspline8(xw, bs);
        #pragma unroll
        for (int k = 0; k < 8; k++) accQ[k] = fmaf(att, bs[k], accQ[k]);
    }
    atomicAdd(&g_PQ[b * 1152 + f], accP);
    #pragma unroll
    for (int k = 0; k < 8; k++)
        atomicAdd(&g_PQ[b * 1152 + 128 + f * 8 + k], accQ[k]);
}

// ---------------------------------------------------------------------------
// K9: combined = [current/S , h_prev]
// ---------------------------------------------------------------------------
__global__ void combine_kernel(const float* __restrict__ h_prev) {
    int idx = blockIdx.x * blockDim.x + threadIdx.x;
    if (idx >= B_ * 2 * U_) return;
    int b = idx / (2 * U_), c = idx - b * 2 * U_;
    float v = (c < U_) ? g_cur[b * U_ + c] * (1.0f / (float)S_)
                       : h_prev[b * U_ + (c - U_)];
    g_comb[idx] = v;
}

// ---------------------------------------------------------------------------
// K10: LSTM elementwise -> out = [h_new (B*U) | c_new (B*U)]
// ---------------------------------------------------------------------------
__global__ void final_kernel(const float* __restrict__ c_prev, float* __restrict__ out) {
    int idx = blockIdx.x * blockDim.x + threadIdx.x;
    if (idx >= B_ * U_) return;
    float f = sigmoidf_(g_gates[idx]);
    float i = sigmoidf_(g_gates[32768 + idx]);
    float cand = tanhf(g_gates[65536 + idx]);
    float o = sigmoidf_(g_gates[98304 + idx]);
    float c = f * c_prev[idx] + i * cand;
    float h = o * tanhf(c);
    out[idx] = h;
    out[B_ * U_ + idx] = c;
}

// ---------------------------------------------------------------------------
// Host launcher
// ---------------------------------------------------------------------------
extern "C" void kernel_launch(void* const* d_in, const int* in_sizes, int n_in,
                              void* d_out, int out_size) {
    const float* x        = (const float*)d_in[0];
    const float* h_prev   = (const float*)d_in[1];
    const float* c_prev   = (const float*)d_in[2];
    const float* tk       = (const float*)d_in[3];
    const float* base_w   = (const float*)d_in[4];
    const float* spline_w = (const float*)d_in[5];
    const float* w1       = (const float*)d_in[6];
    const float* b1       = (const float*)d_in[7];
    const float* w2       = (const float*)d_in[8];
    const float* b2       = (const float*)d_in[9];
    const float* w3       = (const float*)d_in[10];
    const float* b3       = (const float*)d_in[11];
    const float* w4       = (const float*)d_in[12];
    const float* b4       = (const float*)d_in[13];
    const float* ws       = (const float*)d_in[14];
    const float* bsk      = (const float*)d_in[15];
    const float* gamma    = (const float*)d_in[16];
    const float* beta     = (const float*)d_in[17];
    const float* wf       = (const float*)d_in[18];
    const float* bf       = (const float*)d_in[19];
    const float* wi       = (const float*)d_in[20];
    const float* bi       = (const float*)d_in[21];
    const float* wc       = (const float*)d_in[22];
    const float* bc       = (const float*)d_in[23];
    const float* wo       = (const float*)d_in[24];
    const float* bo       = (const float*)d_in[25];
    float* out = (float*)d_out;

    float *p_sig, *p_z1, *p_yskip, *p_h2, *p_g3, *p_g4, *p_PQ, *p_Wc, *p_cur, *p_comb, *p_gates;
    cudaGetSymbolAddress((void**)&p_sig,   g_sig);
    cudaGetSymbolAddress((void**)&p_z1,    g_z1);
    cudaGetSymbolAddress((void**)&p_yskip, g_yskip);
    cudaGetSymbolAddress((void**)&p_h2,    g_h2);
    cudaGetSymbolAddress((void**)&p_g3,    g_g3);
    cudaGetSymbolAddress((void**)&p_g4,    g_g4);
    cudaGetSymbolAddress((void**)&p_PQ,    g_PQ);
    cudaGetSymbolAddress((void**)&p_Wc,    g_Wc);
    cudaGetSymbolAddress((void**)&p_cur,   g_cur);
    cudaGetSymbolAddress((void**)&p_comb,  g_comb);
    cudaGetSymbolAddress((void**)&p_gates, g_gates);

    // 1) init
    init_sig_kernel<<<(B_ * SIGDIM + 255) / 256, 256>>>(x, tk);
    init_small_kernel<<<(9 * 32768 + 32768 + 73728 + 255) / 256, 256>>>(b1, bsk, b2, b3, b4, bf, bi, bc, bo);
    wc_transpose_kernel<<<(1152 * U_ + 255) / 256, 256>>>(base_w, spline_w);

    // 2) signature level-2 (batched GEMM, split-K=4)
    sig2_kernel<<<dim3(4, B_), 256>>>(x, tk);

    // 3) big sig projections: (64,16512)@(16512,512)
    gemm64_acc<<<dim3(4, 32), 256>>>(p_sig, SIGDIM, w1, U_, p_z1, U_, SIGDIM, 516, 0);
    gemm64_acc<<<dim3(4, 32), 256>>>(p_sig, SIGDIM, ws, U_, p_yskip, U_, SIGDIM, 516, 0);

    // 4) GRN: h2 = elu(z1)@w2 + b2 ; g3/g4
    gemm64_acc<<<dim3(4, 4), 256>>>(p_z1, U_, w2, U_, p_h2, U_, U_, 128, 1);
    gemm64_acc<<<dim3(4, 4), 256>>>(p_h2, U_, w3, U_, p_g3, U_, U_, 128, 0);
    gemm64_acc<<<dim3(4, 4), 256>>>(p_h2, U_, w4, U_, p_g4, U_, U_, 128, 0);
    glu_y_kernel<<<(B_ * U_ + 255) / 256, 256>>>();
    ln_softmax_kernel<<<B_, U_>>>(gamma, beta);

    // 5) attention-weighted KAN reductions P,Q then current = PQ @ Wc / S
    pq_kernel<<<dim3(B_, 4), 128>>>(x, tk);
    gemm64_acc<<<dim3(4, 8), 256>>>(p_PQ, 1152, p_Wc, U_, p_cur, U_, 1152, 144, 0);

    // 6) LSTM
    combine_kernel<<<(B_ * 2 * U_ + 255) / 256, 256>>>(h_prev);
    gemm64_acc<<<dim3(4, 8), 256>>>(p_comb, 2 * U_, wf, U_, p_gates,          U_, 2 * U_, 128, 0);
    gemm64_acc<<<dim3(4, 8), 256>>>(p_comb, 2 * U_, wi, U_, p_gates + 32768,  U_, 2 * U_, 128, 0);
    gemm64_acc<<<dim3(4, 8), 256>>>(p_comb, 2 * U_, wc, U_, p_gates + 65536,  U_, 2 * U_, 128, 0);
    gemm64_acc<<<dim3(4, 8), 256>>>(p_comb, 2 * U_, wo, U_, p_gates + 98304,  U_, 2 * U_, 128, 0);
    final_kernel<<<(B_ * U_ + 255) / 256, 256>>>(c_prev, out);
}

// round 6
// speedup vs baseline: 1.2682x; 1.2682x over previous
#include <cuda_runtime.h>
#include <math.h>

// ---------------------------------------------------------------------------
// Problem constants
// ---------------------------------------------------------------------------
#define B_   64
#define S_   512
#define F_   128
#define U_   512
#define SIGDIM 16512            // F + F*F
#define NB_  8
#define LN_EPS 1e-3f

// ---------------------------------------------------------------------------
// Device scratch
// ---------------------------------------------------------------------------
__device__ float g_sig  [B_ * SIGDIM];      // s1 | vec(s2)
__device__ float g_M    [B_ * F_ * F_];     // M = sum_t w_t (x) w_{t+1}
__device__ float g_z1   [B_ * U_];
__device__ float g_yskip[B_ * U_];
__device__ float g_h2   [B_ * U_];
__device__ float g_g3   [B_ * U_];
__device__ float g_g4   [B_ * U_];
__device__ float g_attn [B_ * U_];
__device__ float g_PQ   [B_ * 1152];        // [64][128 P | 1024 Q]
__device__ float g_Wc   [1152 * U_];
__device__ float g_cur  [B_ * U_];
__device__ float g_gates[4 * B_ * U_];

struct P4 { const float* p[4]; };
struct O4 { float* p[4]; };

// ---------------------------------------------------------------------------
// Helpers
// ---------------------------------------------------------------------------
__device__ __forceinline__ float fsigmoid(float x) { return 1.0f / (1.0f + __expf(-x)); }

__device__ __forceinline__ float blockReduceSum(float v, float* smem) {
    int lane = threadIdx.x & 31, w = threadIdx.x >> 5;
    #pragma unroll
    for (int o = 16; o > 0; o >>= 1) v += __shfl_xor_sync(0xffffffffu, v, o);
    if (lane == 0) smem[w] = v;
    __syncthreads();
    int nw = blockDim.x >> 5;
    float r = (threadIdx.x < nw) ? smem[threadIdx.x] : 0.0f;
    if (w == 0) {
        #pragma unroll
        for (int o = 16; o > 0; o >>= 1) r += __shfl_xor_sync(0xffffffffu, r, o);
        if (lane == 0) smem[0] = r;
    }
    __syncthreads();
    float out = smem[0];
    __syncthreads();
    return out;
}

__device__ __forceinline__ float blockReduceMax(float v, float* smem) {
    int lane = threadIdx.x & 31, w = threadIdx.x >> 5;
    #pragma unroll
    for (int o = 16; o > 0; o >>= 1) v = fmaxf(v, __shfl_xor_sync(0xffffffffu, v, o));
    if (lane == 0) smem[w] = v;
    __syncthreads();
    int nw = blockDim.x >> 5;
    float r = (threadIdx.x < nw) ? smem[threadIdx.x] : -INFINITY;
    if (w == 0) {
        #pragma unroll
        for (int o = 16; o > 0; o >>= 1) r = fmaxf(r, __shfl_xor_sync(0xffffffffu, r, o));
        if (lane == 0) smem[0] = r;
    }
    __syncthreads();
    float out = smem[0];
    __syncthreads();
    return out;
}

// b-spline basis (grid_size=5, order=3), exact Cox-de Boor as reference
__device__ __forceinline__ void bspline8(float x, float* out) {
    float b[11];
    #pragma unroll
    for (int i = 0; i < 11; i++) {
        float gi  = -1.0f + 0.4f * (float)(i - 3);
        float gi1 = -1.0f + 0.4f * (float)(i - 2);
        b[i] = (x >= gi && x < gi1) ? 1.0f : 0.0f;
    }
    #pragma unroll
    for (int p = 1; p <= 3; p++) {
        float inv = 1.0f / (0.4f * (float)p);
        #pragma unroll
        for (int i = 0; i < 11 - p; i++) {
            float gi   = -1.0f + 0.4f * (float)(i - 3);
            float gip1 = -1.0f + 0.4f * (float)(i + p + 1 - 3);
            b[i] = (x - gi) * inv * b[i] + (gip1 - x) * inv * b[i + 1];
        }
    }
    #pragma unroll
    for (int k = 0; k < 8; k++) out[k] = b[k];
}

// ---------------------------------------------------------------------------
// K1: bias/zero init for all accumulated buffers
// ---------------------------------------------------------------------------
__global__ void init_small_kernel(const float* b1, const float* bsk, const float* b2,
                                  const float* b3, const float* b4,
                                  const float* bf, const float* bi,
                                  const float* bc, const float* bo) {
    int idx = blockIdx.x * blockDim.x + threadIdx.x;
    const int NBIAS = 9 * B_ * U_;                 // 294912
    const int NCUR = B_ * U_, NPQ = B_ * 1152, NM = B_ * F_ * F_;
    if (idx < NBIAS) {
        int which = idx >> 15;
        int r = idx & 32767;
        int u = r & (U_ - 1);
        float v; float* dst;
        switch (which) {
            case 0: dst = g_z1;            v = b1[u];  break;
            case 1: dst = g_yskip;         v = bsk[u]; break;
            case 2: dst = g_h2;            v = b2[u];  break;
            case 3: dst = g_g3;            v = b3[u];  break;
            case 4: dst = g_g4;            v = b4[u];  break;
            case 5: dst = g_gates;         v = bf[u];  break;
            case 6: dst = g_gates + 32768; v = bi[u];  break;
            case 7: dst = g_gates + 65536; v = bc[u];  break;
            default: dst = g_gates + 98304; v = bo[u]; break;
        }
        dst[r] = v;
    } else {
        int r = idx - NBIAS;
        if (r < NCUR) { g_cur[r] = 0.0f; return; }
        r -= NCUR;
        if (r < NPQ) { g_PQ[r] = 0.0f; return; }
        r -= NPQ;
        if (r < NM) g_M[r] = 0.0f;
    }
}

// ---------------------------------------------------------------------------
// K2: build combined KAN weight Wc[k][u]
// ---------------------------------------------------------------------------
__global__ void wc_transpose_kernel(const float* __restrict__ base_w,
                                    const float* __restrict__ spline_w) {
    int idx = blockIdx.x * blockDim.x + threadIdx.x;
    if (idx >= 1152 * U_) return;
    int k = idx / U_, u = idx - k * U_;
    float v;
    if (k < F_) v = base_w[k * U_ + u];
    else {
        int kk = k - F_;
        int f = kk >> 3, s = kk & 7;
        v = spline_w[(u * F_ + f) * NB_ + s];
    }
    g_Wc[idx] = v;
}

// ---------------------------------------------------------------------------
// K3: M[b,i,j] = sum_t w_t[i] * w_{t+1}[j], split-K over 8 chunks of 64 t.
// Single staged array Ws (rows t0..t0+32); a = Ws[kk], d = Ws[kk+1].
// ---------------------------------------------------------------------------
__global__ void __launch_bounds__(256) sig2_kernel(const float* __restrict__ x,
                                                   const float* __restrict__ tk) {
    int b = blockIdx.y;
    int tBegin = blockIdx.x * 64;
    int tEnd = min(S_ - 1, tBegin + 64);           // products t in [tBegin, tEnd)

    __shared__ float Ws[33][128];

    int tid = threadIdx.x;
    int tx = tid & 15, ty = tid >> 4;
    const float* xb = x + b * S_ * F_;

    float acc[8][8];
    #pragma unroll
    for (int i = 0; i < 8; i++)
        #pragma unroll
        for (int j = 0; j < 8; j++) acc[i][j] = 0.0f;

    for (int t0 = tBegin; t0 < tEnd; t0 += 32) {
        int nt = min(32, tEnd - t0);
        for (int e = tid; e < (nt + 1) * 128; e += 256) {
            int kk = e >> 7, f = e & 127;
            Ws[kk][f] = tk[t0 + kk] * xb[(t0 + kk) * F_ + f];
        }
        __syncthreads();
        #pragma unroll 8
        for (int kk = 0; kk < nt; kk++) {
            float a8[8], d8[8];
            *(float4*)&a8[0] = *(const float4*)&Ws[kk][ty * 8];
            *(float4*)&a8[4] = *(const float4*)&Ws[kk][ty * 8 + 4];
            *(float4*)&d8[0] = *(const float4*)&Ws[kk + 1][tx * 8];
            *(float4*)&d8[4] = *(const float4*)&Ws[kk + 1][tx * 8 + 4];
            #pragma unroll
            for (int i = 0; i < 8; i++)
                #pragma unroll
                for (int j = 0; j < 8; j++) acc[i][j] = fmaf(a8[i], d8[j], acc[i][j]);
        }
        __syncthreads();
    }

    float* Mb = g_M + b * F_ * F_;
    #pragma unroll
    for (int i = 0; i < 8; i++)
        #pragma unroll
        for (int j = 0; j < 8; j++)
            atomicAdd(&Mb[(ty * 8 + i) * F_ + tx * 8 + j], acc[i][j]);
}

// ---------------------------------------------------------------------------
// K4: sig epilogue: s2 = 0.5(M - M^T) + 0.5 wL(x)wL + 0.5 w0(x)w0 - w0(x)wL
//     plus s1 = wL - w0
// ---------------------------------------------------------------------------
__global__ void sig_epi_kernel(const float* __restrict__ x, const float* __restrict__ tk) {
    int idx = blockIdx.x * blockDim.x + threadIdx.x;
    const int total = B_ * F_ * F_;
    float tk0 = tk[0], tkL = tk[S_ - 1];
    if (idx < total) {
        int b = idx >> 14, r = idx & 16383, i = r >> 7, j = r & 127;
        const float* xb = x + b * S_ * F_;
        float w0i = tk0 * xb[i],               w0j = tk0 * xb[j];
        float wLi = tkL * xb[(S_ - 1) * F_ + i], wLj = tkL * xb[(S_ - 1) * F_ + j];
        float v = 0.5f * (g_M[idx] - g_M[(b << 14) + (j << 7) + i])
                + 0.5f * wLi * wLj + 0.5f * w0i * w0j - w0i * wLj;
        g_sig[b * SIGDIM + F_ + r] = v;
    } else {
        int r2 = idx - total;
        if (r2 < B_ * F_) {
            int b = r2 >> 7, c = r2 & 127;
            g_sig[b * SIGDIM + c] = tkL * x[(b * S_ + S_ - 1) * F_ + c] - tk0 * x[b * S_ * F_ + c];
        }
    }
}

// ---------------------------------------------------------------------------
// K5: generic GEMM, M=64, N-tile 128, 128 threads, 8x8/thread, split-K atomics.
// A sourced from A (k<kHalf, scaled by ascale) else A2. Optional elu on A.
// B / C selected by blockIdx.z.
// ---------------------------------------------------------------------------
__global__ void __launch_bounds__(128) gemm64(
    const float* __restrict__ A, int lda, float ascale,
    const float* __restrict__ A2, int lda2, int kHalf,
    int actElu, int K, int kChunk,
    P4 Bset, int ldb, O4 Cset, int ldc)
{
    const float* __restrict__ Bw = Bset.p[blockIdx.z];
    float* __restrict__ C = Cset.p[blockIdx.z];
    int n0 = blockIdx.x * 128;
    int kBegin = blockIdx.y * kChunk;
    int kEnd = min(K, kBegin + kChunk);

    __shared__ float As[16][68];
    __shared__ float Bs[16][128];

    int tid = threadIdx.x;
    int tx = tid & 15, ty = tid >> 4;     // tx: 8-col groups, ty: 8-row groups

    float acc[8][8];
    #pragma unroll
    for (int i = 0; i < 8; i++)
        #pragma unroll
        for (int j = 0; j < 8; j++) acc[i][j] = 0.0f;

    for (int k0 = kBegin; k0 < kEnd; k0 += 16) {
        // A tile: 64 x 16 (256 float4, 2 per thread)
        #pragma unroll
        for (int it = 0; it < 2; it++) {
            int e = tid + it * 128;
            int m = e >> 2;
            int kq = (e & 3) << 2;
            int k = k0 + kq;
            float4 v = make_float4(0.f, 0.f, 0.f, 0.f);
            if (k < kEnd) {
                if (k < kHalf) {
                    v = *(const float4*)&A[m * lda + k];
                    v.x *= ascale; v.y *= ascale; v.z *= ascale; v.w *= ascale;
                } else {
                    v = *(const float4*)&A2[m * lda2 + (k - kHalf)];
                }
            }
            if (actElu) {
                v.x = (v.x > 0.f) ? v.x : (__expf(v.x) - 1.f);
                v.y = (v.y > 0.f) ? v.y : (__expf(v.y) - 1.f);
                v.z = (v.z > 0.f) ? v.z : (__expf(v.z) - 1.f);
                v.w = (v.w > 0.f) ? v.w : (__expf(v.w) - 1.f);
            }
            As[kq + 0][m] = v.x; As[kq + 1][m] = v.y;
            As[kq + 2][m] = v.z; As[kq + 3][m] = v.w;
        }
        // B tile: 16 x 128 (512 float4, 4 per thread)
        #pragma unroll
        for (int it = 0; it < 4; it++) {
            int e = tid + it * 128;
            int kk = e >> 5;
            int nq = (e & 31) << 2;
            int k = k0 + kk;
            float4 v = make_float4(0.f, 0.f, 0.f, 0.f);
            if (k < kEnd) v = *(const float4*)&Bw[k * ldb + n0 + nq];
            *(float4*)&Bs[kk][nq] = v;
        }
        __syncthreads();
        #pragma unroll
        for (int kk = 0; kk < 16; kk++) {
            float a8[8], b8[8];
            *(float4*)&a8[0] = *(const float4*)&As[kk][ty * 8];
            *(float4*)&a8[4] = *(const float4*)&As[kk][ty * 8 + 4];
            *(float4*)&b8[0] = *(const float4*)&Bs[kk][tx * 8];
            *(float4*)&b8[4] = *(const float4*)&Bs[kk][tx * 8 + 4];
            #pragma unroll
            for (int i = 0; i < 8; i++)
                #pragma unroll
                for (int j = 0; j < 8; j++) acc[i][j] = fmaf(a8[i], b8[j], acc[i][j]);
        }
        __syncthreads();
    }
    #pragma unroll
    for (int i = 0; i < 8; i++)
        #pragma unroll
        for (int j = 0; j < 8; j++)
            atomicAdd(&C[(ty * 8 + i) * ldc + n0 + tx * 8 + j], acc[i][j]);
}

// ---------------------------------------------------------------------------
// K6: fused glu + layernorm + softmax -> attn
// ---------------------------------------------------------------------------
__global__ void ln_softmax_kernel(const float* __restrict__ gamma,
                                  const float* __restrict__ beta) {
    __shared__ float red[32];
    int b = blockIdx.x, u = threadIdx.x;
    int idx = b * U_ + u;
    float v = g_yskip[idx] + fsigmoid(g_g3[idx]) * g_g4[idx];
    float mu = blockReduceSum(v, red) * (1.0f / (float)U_);
    float d = v - mu;
    float var = blockReduceSum(d * d, red) * (1.0f / (float)U_);
    float yn = d * rsqrtf(var + LN_EPS) * gamma[u] + beta[u];
    float mx = blockReduceMax(yn, red);
    float e = __expf(yn - mx);
    float s = blockReduceSum(e, red);
    g_attn[idx] = e / s;
}

// ---------------------------------------------------------------------------
// K7: P[b,f] = sum_s attn*silu(w), Q[b,f,k] = sum_s attn*bspl_k(w)
// ---------------------------------------------------------------------------
__global__ void __launch_bounds__(128) pq_kernel(const float* __restrict__ x,
                                                 const float* __restrict__ tk) {
    int b = blockIdx.x, chunk = blockIdx.y;
    int f = threadIdx.x;
    int s0 = chunk * 128;

    __shared__ float att_s[128], tk_s[128];
    att_s[f] = g_attn[b * U_ + s0 + f];
    tk_s[f]  = tk[s0 + f];
    __syncthreads();

    float accP = 0.0f, accQ[8];
    #pragma unroll
    for (int k = 0; k < 8; k++) accQ[k] = 0.0f;

    const float* xb = x + (b * S_ + s0) * F_;
    for (int si = 0; si < 128; si++) {
        float att = att_s[si];
        float xw = tk_s[si] * xb[si * F_ + f];
        float sg = fsigmoid(xw);
        accP = fmaf(att, xw * sg, accP);
        float bs[8];
        bspline8(xw, bs);
        #pragma unroll
        for (int k = 0; k < 8; k++) accQ[k] = fmaf(att, bs[k], accQ[k]);
    }
    atomicAdd(&g_PQ[b * 1152 + f], accP);
    #pragma unroll
    for (int k = 0; k < 8; k++)
        atomicAdd(&g_PQ[b * 1152 + 128 + f * 8 + k], accQ[k]);
}

// ---------------------------------------------------------------------------
// K8: LSTM elementwise -> out = [h_new | c_new]
// ---------------------------------------------------------------------------
__global__ void final_kernel(const float* __restrict__ c_prev, float* __restrict__ out) {
    int idx = blockIdx.x * blockDim.x + threadIdx.x;
    if (idx >= B_ * U_) return;
    float f = fsigmoid(g_gates[idx]);
    float i = fsigmoid(g_gates[32768 + idx]);
    float cand = tanhf(g_gates[65536 + idx]);
    float o = fsigmoid(g_gates[98304 + idx]);
    float c = f * c_prev[idx] + i * cand;
    float h = o * tanhf(c);
    out[idx] = h;
    out[B_ * U_ + idx] = c;
}

// ---------------------------------------------------------------------------
// Host launcher
// ---------------------------------------------------------------------------
extern "C" void kernel_launch(void* const* d_in, const int* in_sizes, int n_in,
                              void* d_out, int out_size) {
    const float* x        = (const float*)d_in[0];
    const float* h_prev   = (const float*)d_in[1];
    const float* c_prev   = (const float*)d_in[2];
    const float* tk       = (const float*)d_in[3];
    const float* base_w   = (const float*)d_in[4];
    const float* spline_w = (const float*)d_in[5];
    const float* w1       = (const float*)d_in[6];
    const float* b1       = (const float*)d_in[7];
    const float* w2       = (const float*)d_in[8];
    const float* b2       = (const float*)d_in[9];
    const float* w3       = (const float*)d_in[10];
    const float* b3       = (const float*)d_in[11];
    const float* w4       = (const float*)d_in[12];
    const float* b4       = (const float*)d_in[13];
    const float* ws       = (const float*)d_in[14];
    const float* bsk      = (const float*)d_in[15];
    const float* gamma    = (const float*)d_in[16];
    const float* beta     = (const float*)d_in[17];
    const float* wf       = (const float*)d_in[18];
    const float* bf       = (const float*)d_in[19];
    const float* wi       = (const float*)d_in[20];
    const float* bi       = (const float*)d_in[21];
    const float* wc       = (const float*)d_in[22];
    const float* bc       = (const float*)d_in[23];
    const float* wo       = (const float*)d_in[24];
    const float* bo       = (const float*)d_in[25];
    float* out = (float*)d_out;

    float *p_sig, *p_z1, *p_yskip, *p_h2, *p_g3, *p_g4, *p_PQ, *p_Wc, *p_cur, *p_gates;
    cudaGetSymbolAddress((void**)&p_sig,   g_sig);
    cudaGetSymbolAddress((void**)&p_z1,    g_z1);
    cudaGetSymbolAddress((void**)&p_yskip, g_yskip);
    cudaGetSymbolAddress((void**)&p_h2,    g_h2);
    cudaGetSymbolAddress((void**)&p_g3,    g_g3);
    cudaGetSymbolAddress((void**)&p_g4,    g_g4);
    cudaGetSymbolAddress((void**)&p_PQ,    g_PQ);
    cudaGetSymbolAddress((void**)&p_Wc,    g_Wc);
    cudaGetSymbolAddress((void**)&p_cur,   g_cur);
    cudaGetSymbolAddress((void**)&p_gates, g_gates);

    const int NINIT = 9 * 32768 + 32768 + 73728 + B_ * F_ * F_;

    // 1) init + weight reshuffle
    init_small_kernel<<<(NINIT + 255) / 256, 256>>>(b1, bsk, b2, b3, b4, bf, bi, bc, bo);
    wc_transpose_kernel<<<(1152 * U_ + 255) / 256, 256>>>(base_w, spline_w);

    // 2) signature level-2 via M = sum_t w_t (x) w_{t+1}, then epilogue
    sig2_kernel<<<dim3(8, B_), 256>>>(x, tk);
    sig_epi_kernel<<<(B_ * F_ * F_ + B_ * F_ + 255) / 256, 256>>>(x, tk);

    // 3) fused big sig projections: z1 = sig@w1+b1, yskip = sig@ws+bs
    {
        P4 Bb; Bb.p[0] = w1; Bb.p[1] = ws; Bb.p[2] = w1; Bb.p[3] = w1;
        O4 Cb; Cb.p[0] = p_z1; Cb.p[1] = p_yskip; Cb.p[2] = p_z1; Cb.p[3] = p_z1;
        gemm64<<<dim3(4, 32, 2), 128>>>(p_sig, SIGDIM, 1.0f, p_sig, SIGDIM, SIGDIM,
                                        0, SIGDIM, 516, Bb, U_, Cb, U_);
    }
    // 4) GRN: h2 = elu(z1)@w2+b2 ; then g3,g4 fused
    {
        P4 Bb; Bb.p[0] = w2; Bb.p[1] = w2; Bb.p[2] = w2; Bb.p[3] = w2;
        O4 Cb; Cb.p[0] = p_h2; Cb.p[1] = p_h2; Cb.p[2] = p_h2; Cb.p[3] = p_h2;
        gemm64<<<dim3(4, 16, 1), 128>>>(p_z1, U_, 1.0f, p_z1, U_, U_,
                                        1, U_, 32, Bb, U_, Cb, U_);
    }
    {
        P4 Bb; Bb.p[0] = w3; Bb.p[1] = w4; Bb.p[2] = w3; Bb.p[3] = w3;
        O4 Cb; Cb.p[0] = p_g3; Cb.p[1] = p_g4; Cb.p[2] = p_g3; Cb.p[3] = p_g3;
        gemm64<<<dim3(4, 16, 2), 128>>>(p_h2, U_, 1.0f, p_h2, U_, U_,
                                        0, U_, 32, Bb, U_, Cb, U_);
    }
    // 5) glu + LN + softmax fused
    ln_softmax_kernel<<<B_, U_>>>(gamma, beta);

    // 6) attention-weighted KAN reductions, then current = PQ @ Wc
    pq_kernel<<<dim3(B_, 4), 128>>>(x, tk);
    {
        P4 Bb; Bb.p[0] = p_Wc; Bb.p[1] = p_Wc; Bb.p[2] = p_Wc; Bb.p[3] = p_Wc;
        O4 Cb; Cb.p[0] = p_cur; Cb.p[1] = p_cur; Cb.p[2] = p_cur; Cb.p[3] = p_cur;
        gemm64<<<dim3(4, 18, 1), 128>>>(p_PQ, 1152, 1.0f, p_PQ, 1152, 1152,
                                        0, 1152, 64, Bb, U_, Cb, U_);
    }
    // 7) LSTM gates: A = [cur/S , h_prev] via dual-source loader; 4 gates fused
    {
        P4 Bb; Bb.p[0] = wf; Bb.p[1] = wi; Bb.p[2] = wc; Bb.p[3] = wo;
        O4 Cb; Cb.p[0] = p_gates; Cb.p[1] = p_gates + 32768;
        Cb.p[2] = p_gates + 65536; Cb.p[3] = p_gates + 98304;
        gemm64<<<dim3(4, 16, 4), 128>>>(p_cur, U_, 1.0f / (float)S_, h_prev, U_, U_,
                                        0, 2 * U_, 64, Bb, U_, Cb, U_);
    }
    // 8) LSTM elementwise
    final_kernel<<<(B_ * U_ + 255) / 256, 256>>>(c_prev, out);
}

// round 7
// speedup vs baseline: 1.3497x; 1.0643x over previous
#include <cuda_runtime.h>
#include <math.h>

// ---------------------------------------------------------------------------
// Problem constants
// ---------------------------------------------------------------------------
#define B_   64
#define S_   512
#define F_   128
#define U_   512
#define SIGDIM 16512            // F + F*F
#define NB_  8
#define LN_EPS 1e-3f

// ---------------------------------------------------------------------------
// Device scratch
// ---------------------------------------------------------------------------
__device__ float g_sig  [B_ * SIGDIM];      // s1 | vec(s2)
__device__ float g_M    [B_ * F_ * F_];     // M = sum_t w_t (x) w_{t+1}
__device__ float g_z1   [B_ * U_];
__device__ float g_yskip[B_ * U_];
__device__ float g_h2   [B_ * U_];
__device__ float g_g3   [B_ * U_];
__device__ float g_g4   [B_ * U_];
__device__ float g_attn [B_ * U_];
__device__ float g_PQ   [B_ * 1152];        // [64][128 P | 1024 Q]
__device__ float g_Wc   [1152 * U_];
__device__ float g_cur  [B_ * U_];
__device__ float g_gates[4 * B_ * U_];

struct P4 { const float* p[4]; };
struct O4 { float* p[4]; };

// ---------------------------------------------------------------------------
// Helpers
// ---------------------------------------------------------------------------
__device__ __forceinline__ float fsigmoid(float x) { return 1.0f / (1.0f + __expf(-x)); }

__device__ __forceinline__ float blockReduceSum(float v, float* smem) {
    int lane = threadIdx.x & 31, w = threadIdx.x >> 5;
    #pragma unroll
    for (int o = 16; o > 0; o >>= 1) v += __shfl_xor_sync(0xffffffffu, v, o);
    if (lane == 0) smem[w] = v;
    __syncthreads();
    int nw = blockDim.x >> 5;
    float r = (threadIdx.x < nw) ? smem[threadIdx.x] : 0.0f;
    if (w == 0) {
        #pragma unroll
        for (int o = 16; o > 0; o >>= 1) r += __shfl_xor_sync(0xffffffffu, r, o);
        if (lane == 0) smem[0] = r;
    }
    __syncthreads();
    float out = smem[0];
    __syncthreads();
    return out;
}

__device__ __forceinline__ float blockReduceMax(float v, float* smem) {
    int lane = threadIdx.x & 31, w = threadIdx.x >> 5;
    #pragma unroll
    for (int o = 16; o > 0; o >>= 1) v = fmaxf(v, __shfl_xor_sync(0xffffffffu, v, o));
    if (lane == 0) smem[w] = v;
    __syncthreads();
    int nw = blockDim.x >> 5;
    float r = (threadIdx.x < nw) ? smem[threadIdx.x] : -INFINITY;
    if (w == 0) {
        #pragma unroll
        for (int o = 16; o > 0; o >>= 1) r = fmaxf(r, __shfl_xor_sync(0xffffffffu, r, o));
        if (lane == 0) smem[0] = r;
    }
    __syncthreads();
    float out = smem[0];
    __syncthreads();
    return out;
}

// b-spline basis (grid_size=5, order=3), exact Cox-de Boor as reference
__device__ __forceinline__ void bspline8(float x, float* out) {
    float b[11];
    #pragma unroll
    for (int i = 0; i < 11; i++) {
        float gi  = -1.0f + 0.4f * (float)(i - 3);
        float gi1 = -1.0f + 0.4f * (float)(i - 2);
        b[i] = (x >= gi && x < gi1) ? 1.0f : 0.0f;
    }
    #pragma unroll
    for (int p = 1; p <= 3; p++) {
        float inv = 1.0f / (0.4f * (float)p);
        #pragma unroll
        for (int i = 0; i < 11 - p; i++) {
            float gi   = -1.0f + 0.4f * (float)(i - 3);
            float gip1 = -1.0f + 0.4f * (float)(i + p + 1 - 3);
            b[i] = (x - gi) * inv * b[i] + (gip1 - x) * inv * b[i + 1];
        }
    }
    #pragma unroll
    for (int k = 0; k < 8; k++) out[k] = b[k];
}

// ---------------------------------------------------------------------------
// K1: bias/zero init + base_w copy into Wc
// ---------------------------------------------------------------------------
__global__ void init_small_kernel(const float* b1, const float* bsk, const float* b2,
                                  const float* b3, const float* b4,
                                  const float* bf, const float* bi,
                                  const float* bc, const float* bo,
                                  const float* base_w) {
    int idx = blockIdx.x * blockDim.x + threadIdx.x;
    const int NBIAS = 9 * B_ * U_;                 // 294912
    const int NCUR = B_ * U_, NPQ = B_ * 1152, NM = B_ * F_ * F_;
    const int NBASE = F_ * U_;                     // 65536
    if (idx < NBIAS) {
        int which = idx >> 15;
        int r = idx & 32767;
        int u = r & (U_ - 1);
        float v; float* dst;
        switch (which) {
            case 0: dst = g_z1;            v = b1[u];  break;
            case 1: dst = g_yskip;         v = bsk[u]; break;
            case 2: dst = g_h2;            v = b2[u];  break;
            case 3: dst = g_g3;            v = b3[u];  break;
            case 4: dst = g_g4;            v = b4[u];  break;
            case 5: dst = g_gates;         v = bf[u];  break;
            case 6: dst = g_gates + 32768; v = bi[u];  break;
            case 7: dst = g_gates + 65536; v = bc[u];  break;
            default: dst = g_gates + 98304; v = bo[u]; break;
        }
        dst[r] = v;
    } else {
        int r = idx - NBIAS;
        if (r < NCUR) { g_cur[r] = 0.0f; return; }
        r -= NCUR;
        if (r < NPQ) { g_PQ[r] = 0.0f; return; }
        r -= NPQ;
        if (r < NM) { g_M[r] = 0.0f; return; }
        r -= NM;
        if (r < NBASE) g_Wc[r] = base_w[r];        // base_w already [k][u]
    }
}

// ---------------------------------------------------------------------------
// K2: tiled transpose of spline_w (512 x 1024) into Wc rows [128..1152)
// Wc[128+kk][u] = spline_w[u][kk]
// ---------------------------------------------------------------------------
__global__ void __launch_bounds__(256) wc_spline_T(const float* __restrict__ spline_w) {
    __shared__ float tile[32][33];
    int kk0 = blockIdx.x * 32, u0 = blockIdx.y * 32;
    int tx = threadIdx.x & 31, ty = threadIdx.x >> 5;   // 32 x 8
    #pragma unroll
    for (int a = 0; a < 32; a += 8)
        tile[ty + a][tx] = spline_w[(u0 + ty + a) * 1024 + kk0 + tx];
    __syncthreads();
    #pragma unroll
    for (int a = 0; a < 32; a += 8)
        g_Wc[(F_ + kk0 + ty + a) * U_ + u0 + tx] = tile[tx][ty + a];
}

// ---------------------------------------------------------------------------
// K3: M[b,i,j] = sum_t w_t[i] * w_{t+1}[j], split-K over 8 chunks of 64 t.
// ---------------------------------------------------------------------------
__global__ void __launch_bounds__(256) sig2_kernel(const float* __restrict__ x,
                                                   const float* __restrict__ tk) {
    int b = blockIdx.y;
    int tBegin = blockIdx.x * 64;
    int tEnd = min(S_ - 1, tBegin + 64);

    __shared__ float Ws[33][128];

    int tid = threadIdx.x;
    int tx = tid & 15, ty = tid >> 4;
    const float* xb = x + b * S_ * F_;

    float acc[8][8];
    #pragma unroll
    for (int i = 0; i < 8; i++)
        #pragma unroll
        for (int j = 0; j < 8; j++) acc[i][j] = 0.0f;

    for (int t0 = tBegin; t0 < tEnd; t0 += 32) {
        int nt = min(32, tEnd - t0);
        for (int e = tid; e < (nt + 1) * 128; e += 256) {
            int kk = e >> 7, f = e & 127;
            Ws[kk][f] = tk[t0 + kk] * xb[(t0 + kk) * F_ + f];
        }
        __syncthreads();
        #pragma unroll 8
        for (int kk = 0; kk < nt; kk++) {
            float a8[8], d8[8];
            *(float4*)&a8[0] = *(const float4*)&Ws[kk][ty * 8];
            *(float4*)&a8[4] = *(const float4*)&Ws[kk][ty * 8 + 4];
            *(float4*)&d8[0] = *(const float4*)&Ws[kk + 1][tx * 8];
            *(float4*)&d8[4] = *(const float4*)&Ws[kk + 1][tx * 8 + 4];
            #pragma unroll
            for (int i = 0; i < 8; i++)
                #pragma unroll
                for (int j = 0; j < 8; j++) acc[i][j] = fmaf(a8[i], d8[j], acc[i][j]);
        }
        __syncthreads();
    }

    float* Mb = g_M + b * F_ * F_;
    #pragma unroll
    for (int i = 0; i < 8; i++)
        #pragma unroll
        for (int j = 0; j < 8; j++)
            atomicAdd(&Mb[(ty * 8 + i) * F_ + tx * 8 + j], acc[i][j]);
}

// ---------------------------------------------------------------------------
// K4: sig epilogue: s2 = 0.5(M - M^T) + 0.5 wL(x)wL + 0.5 w0(x)w0 - w0(x)wL
//     plus s1 = wL - w0
// ---------------------------------------------------------------------------
__global__ void sig_epi_kernel(const float* __restrict__ x, const float* __restrict__ tk) {
    int idx = blockIdx.x * blockDim.x + threadIdx.x;
    const int total = B_ * F_ * F_;
    float tk0 = tk[0], tkL = tk[S_ - 1];
    if (idx < total) {
        int b = idx >> 14, r = idx & 16383, i = r >> 7, j = r & 127;
        const float* xb = x + b * S_ * F_;
        float w0i = tk0 * xb[i],                 w0j = tk0 * xb[j];
        float wLi = tkL * xb[(S_ - 1) * F_ + i], wLj = tkL * xb[(S_ - 1) * F_ + j];
        float v = 0.5f * (g_M[idx] - g_M[(b << 14) + (j << 7) + i])
                + 0.5f * wLi * wLj + 0.5f * w0i * w0j - w0i * wLj;
        g_sig[b * SIGDIM + F_ + r] = v;
    } else {
        int r2 = idx - total;
        if (r2 < B_ * F_) {
            int b = r2 >> 7, c = r2 & 127;
            g_sig[b * SIGDIM + c] = tkL * x[(b * S_ + S_ - 1) * F_ + c] - tk0 * x[b * S_ * F_ + c];
        }
    }
}

// ---------------------------------------------------------------------------
// K5: generic GEMM, M=64, N-tile 128, 128 threads, 8x8/thread, split-K atomics.
// ---------------------------------------------------------------------------
__global__ void __launch_bounds__(128) gemm64(
    const float* __restrict__ A, int lda, float ascale,
    const float* __restrict__ A2, int lda2, int kHalf,
    int actElu, int K, int kChunk,
    P4 Bset, int ldb, O4 Cset, int ldc)
{
    const float* __restrict__ Bw = Bset.p[blockIdx.z];
    float* __restrict__ C = Cset.p[blockIdx.z];
    int n0 = blockIdx.x * 128;
    int kBegin = blockIdx.y * kChunk;
    int kEnd = min(K, kBegin + kChunk);

    __shared__ float As[16][68];
    __shared__ float Bs[16][128];

    int tid = threadIdx.x;
    int tx = tid & 15, ty = tid >> 4;

    float acc[8][8];
    #pragma unroll
    for (int i = 0; i < 8; i++)
        #pragma unroll
        for (int j = 0; j < 8; j++) acc[i][j] = 0.0f;

    for (int k0 = kBegin; k0 < kEnd; k0 += 16) {
        #pragma unroll
        for (int it = 0; it < 2; it++) {
            int e = tid + it * 128;
            int m = e >> 2;
            int kq = (e & 3) << 2;
            int k = k0 + kq;
            float4 v = make_float4(0.f, 0.f, 0.f, 0.f);
            if (k < kEnd) {
                if (k < kHalf) {
                    v = *(const float4*)&A[m * lda + k];
                    v.x *= ascale; v.y *= ascale; v.z *= ascale; v.w *= ascale;
                } else {
                    v = *(const float4*)&A2[m * lda2 + (k - kHalf)];
                }
            }
            if (actElu) {
                v.x = (v.x > 0.f) ? v.x : (__expf(v.x) - 1.f);
                v.y = (v.y > 0.f) ? v.y : (__expf(v.y) - 1.f);
                v.z = (v.z > 0.f) ? v.z : (__expf(v.z) - 1.f);
                v.w = (v.w > 0.f) ? v.w : (__expf(v.w) - 1.f);
            }
            As[kq + 0][m] = v.x; As[kq + 1][m] = v.y;
            As[kq + 2][m] = v.z; As[kq + 3][m] = v.w;
        }
        #pragma unroll
        for (int it = 0; it < 4; it++) {
            int e = tid + it * 128;
            int kk = e >> 5;
            int nq = (e & 31) << 2;
            int k = k0 + kk;
            float4 v = make_float4(0.f, 0.f, 0.f, 0.f);
            if (k < kEnd) v = *(const float4*)&Bw[k * ldb + n0 + nq];
            *(float4*)&Bs[kk][nq] = v;
        }
        __syncthreads();
        #pragma unroll
        for (int kk = 0; kk < 16; kk++) {
            float a8[8], b8[8];
            *(float4*)&a8[0] = *(const float4*)&As[kk][ty * 8];
            *(float4*)&a8[4] = *(const float4*)&As[kk][ty * 8 + 4];
            *(float4*)&b8[0] = *(const float4*)&Bs[kk][tx * 8];
            *(float4*)&b8[4] = *(const float4*)&Bs[kk][tx * 8 + 4];
            #pragma unroll
            for (int i = 0; i < 8; i++)
                #pragma unroll
                for (int j = 0; j < 8; j++) acc[i][j] = fmaf(a8[i], b8[j], acc[i][j]);
        }
        __syncthreads();
    }
    #pragma unroll
    for (int i = 0; i < 8; i++)
        #pragma unroll
        for (int j = 0; j < 8; j++)
            atomicAdd(&C[(ty * 8 + i) * ldc + n0 + tx * 8 + j], acc[i][j]);
}

// ---------------------------------------------------------------------------
// K6: fused glu + layernorm + softmax -> attn
// ---------------------------------------------------------------------------
__global__ void ln_softmax_kernel(const float* __restrict__ gamma,
                                  const float* __restrict__ beta) {
    __shared__ float red[32];
    int b = blockIdx.x, u = threadIdx.x;
    int idx = b * U_ + u;
    float v = g_yskip[idx] + fsigmoid(g_g3[idx]) * g_g4[idx];
    float mu = blockReduceSum(v, red) * (1.0f / (float)U_);
    float d = v - mu;
    float var = blockReduceSum(d * d, red) * (1.0f / (float)U_);
    float yn = d * rsqrtf(var + LN_EPS) * gamma[u] + beta[u];
    float mx = blockReduceMax(yn, red);
    float e = __expf(yn - mx);
    float s = blockReduceSum(e, red);
    g_attn[idx] = e / s;
}

// ---------------------------------------------------------------------------
// K7: P[b,f] = sum_s attn*silu(w), Q[b,f,k] = sum_s attn*bspl_k(w)
// grid (B, 16 s-chunks of 32), block 128 (one thread per f)
// ---------------------------------------------------------------------------
__global__ void __launch_bounds__(128) pq_kernel(const float* __restrict__ x,
                                                 const float* __restrict__ tk) {
    int b = blockIdx.x, chunk = blockIdx.y;
    int f = threadIdx.x;
    int s0 = chunk * 32;

    __shared__ float att_s[32], tk_s[32];
    if (f < 32) {
        att_s[f] = g_attn[b * U_ + s0 + f];
        tk_s[f]  = tk[s0 + f];
    }
    __syncthreads();

    float accP = 0.0f, accQ[8];
    #pragma unroll
    for (int k = 0; k < 8; k++) accQ[k] = 0.0f;

    const float* xb = x + (b * S_ + s0) * F_;
    #pragma unroll 2
    for (int si = 0; si < 32; si++) {
        float att = att_s[si];
        float xw = tk_s[si] * xb[si * F_ + f];
        float sg = fsigmoid(xw);
        accP = fmaf(att, xw * sg, accP);
        float bs[8];
        bspline8(xw, bs);
        #pragma unroll
        for (int k = 0; k < 8; k++) accQ[k] = fmaf(att, bs[k], accQ[k]);
    }
    atomicAdd(&g_PQ[b * 1152 + f], accP);
    #pragma unroll
    for (int k = 0; k < 8; k++)
        atomicAdd(&g_PQ[b * 1152 + 128 + f * 8 + k], accQ[k]);
}

// ---------------------------------------------------------------------------
// K8: LSTM elementwise -> out = [h_new | c_new]
// ---------------------------------------------------------------------------
__global__ void final_kernel(const float* __restrict__ c_prev, float* __restrict__ out) {
    int idx = blockIdx.x * blockDim.x + threadIdx.x;
    if (idx >= B_ * U_) return;
    float f = fsigmoid(g_gates[idx]);
    float i = fsigmoid(g_gates[32768 + idx]);
    float cand = tanhf(g_gates[65536 + idx]);
    float o = fsigmoid(g_gates[98304 + idx]);
    float c = f * c_prev[idx] + i * cand;
    float h = o * tanhf(c);
    out[idx] = h;
    out[B_ * U_ + idx] = c;
}

// ---------------------------------------------------------------------------
// Host launcher
// ---------------------------------------------------------------------------
extern "C" void kernel_launch(void* const* d_in, const int* in_sizes, int n_in,
                              void* d_out, int out_size) {
    const float* x        = (const float*)d_in[0];
    const float* h_prev   = (const float*)d_in[1];
    const float* c_prev   = (const float*)d_in[2];
    const float* tk       = (const float*)d_in[3];
    const float* base_w   = (const float*)d_in[4];
    const float* spline_w = (const float*)d_in[5];
    const float* w1       = (const float*)d_in[6];
    const float* b1       = (const float*)d_in[7];
    const float* w2       = (const float*)d_in[8];
    const float* b2       = (const float*)d_in[9];
    const float* w3       = (const float*)d_in[10];
    const float* b3       = (const float*)d_in[11];
    const float* w4       = (const float*)d_in[12];
    const float* b4       = (const float*)d_in[13];
    const float* ws       = (const float*)d_in[14];
    const float* bsk      = (const float*)d_in[15];
    const float* gamma    = (const float*)d_in[16];
    const float* beta     = (const float*)d_in[17];
    const float* wf       = (const float*)d_in[18];
    const float* bf       = (const float*)d_in[19];
    const float* wi       = (const float*)d_in[20];
    const float* bi       = (const float*)d_in[21];
    const float* wc       = (const float*)d_in[22];
    const float* bc       = (const float*)d_in[23];
    const float* wo       = (const float*)d_in[24];
    const float* bo       = (const float*)d_in[25];
    float* out = (float*)d_out;

    float *p_sig, *p_z1, *p_yskip, *p_h2, *p_g3, *p_g4, *p_PQ, *p_Wc, *p_cur, *p_gates;
    cudaGetSymbolAddress((void**)&p_sig,   g_sig);
    cudaGetSymbolAddress((void**)&p_z1,    g_z1);
    cudaGetSymbolAddress((void**)&p_yskip, g_yskip);
    cudaGetSymbolAddress((void**)&p_h2,    g_h2);
    cudaGetSymbolAddress((void**)&p_g3,    g_g3);
    cudaGetSymbolAddress((void**)&p_g4,    g_g4);
    cudaGetSymbolAddress((void**)&p_PQ,    g_PQ);
    cudaGetSymbolAddress((void**)&p_Wc,    g_Wc);
    cudaGetSymbolAddress((void**)&p_cur,   g_cur);
    cudaGetSymbolAddress((void**)&p_gates, g_gates);

    const int NINIT = 9 * 32768 + 32768 + 73728 + B_ * F_ * F_ + F_ * U_;

    // 1) init (bias fills, zero fills, base_w -> Wc) + spline transpose
    init_small_kernel<<<(NINIT + 255) / 256, 256>>>(b1, bsk, b2, b3, b4, bf, bi, bc, bo, base_w);
    wc_spline_T<<<dim3(32, 16), 256>>>(spline_w);

    // 2) signature level-2 via M = sum_t w_t (x) w_{t+1}, then epilogue
    sig2_kernel<<<dim3(8, B_), 256>>>(x, tk);
    sig_epi_kernel<<<(B_ * F_ * F_ + B_ * F_ + 255) / 256, 256>>>(x, tk);

    // 3) fused big sig projections: z1 = sig@w1+b1, yskip = sig@ws+bs (920 blocks)
    {
        P4 Bb; Bb.p[0] = w1; Bb.p[1] = ws; Bb.p[2] = w1; Bb.p[3] = w1;
        O4 Cb; Cb.p[0] = p_z1; Cb.p[1] = p_yskip; Cb.p[2] = p_z1; Cb.p[3] = p_z1;
        gemm64<<<dim3(4, 115, 2), 128>>>(p_sig, SIGDIM, 1.0f, p_sig, SIGDIM, SIGDIM,
                                         0, SIGDIM, 144, Bb, U_, Cb, U_);
    }
    // 4) GRN: h2 = elu(z1)@w2+b2 ; then g3,g4 fused
    {
        P4 Bb; Bb.p[0] = w2; Bb.p[1] = w2; Bb.p[2] = w2; Bb.p[3] = w2;
        O4 Cb; Cb.p[0] = p_h2; Cb.p[1] = p_h2; Cb.p[2] = p_h2; Cb.p[3] = p_h2;
        gemm64<<<dim3(4, 32, 1), 128>>>(p_z1, U_, 1.0f, p_z1, U_, U_,
                                        1, U_, 16, Bb, U_, Cb, U_);
    }
    {
        P4 Bb; Bb.p[0] = w3; Bb.p[1] = w4; Bb.p[2] = w3; Bb.p[3] = w3;
        O4 Cb; Cb.p[0] = p_g3; Cb.p[1] = p_g4; Cb.p[2] = p_g3; Cb.p[3] = p_g3;
        gemm64<<<dim3(4, 32, 2), 128>>>(p_h2, U_, 1.0f, p_h2, U_, U_,
                                        0, U_, 16, Bb, U_, Cb, U_);
    }
    // 5) glu + LN + softmax fused
    ln_softmax_kernel<<<B_, U_>>>(gamma, beta);

    // 6) attention-weighted KAN reductions (1024 blocks), then current = PQ @ Wc
    pq_kernel<<<dim3(B_, 16), 128>>>(x, tk);
    {
        P4 Bb; Bb.p[0] = p_Wc; Bb.p[1] = p_Wc; Bb.p[2] = p_Wc; Bb.p[3] = p_Wc;
        O4 Cb; Cb.p[0] = p_cur; Cb.p[1] = p_cur; Cb.p[2] = p_cur; Cb.p[3] = p_cur;
        gemm64<<<dim3(4, 36, 1), 128>>>(p_PQ, 1152, 1.0f, p_PQ, 1152, 1152,
                                        0, 1152, 32, Bb, U_, Cb, U_);
    }
    // 7) LSTM gates: A = [cur/S , h_prev]; 4 gates fused (512 blocks)
    {
        P4 Bb; Bb.p[0] = wf; Bb.p[1] = wi; Bb.p[2] = wc; Bb.p[3] = wo;
        O4 Cb; Cb.p[0] = p_gates; Cb.p[1] = p_gates + 32768;
        Cb.p[2] = p_gates + 65536; Cb.p[3] = p_gates + 98304;
        gemm64<<<dim3(4, 32, 4), 128>>>(p_cur, U_, 1.0f / (float)S_, h_prev, U_, U_,
                                        0, 2 * U_, 32, Bb, U_, Cb, U_);
    }
    // 8) LSTM elementwise
    final_kernel<<<(B_ * U_ + 255) / 256, 256>>>(c_prev, out);
}

// round 8
// speedup vs baseline: 2.0539x; 1.5218x over previous
#include <cuda_runtime.h>
#include <math.h>

// ---------------------------------------------------------------------------
// Problem constants
// ---------------------------------------------------------------------------
#define B_   64
#define S_   512
#define F_   128
#define U_   512
#define SIGDIM 16512            // F + F*F
#define NB_  8
#define LN_EPS 1e-3f
#define NSPLIT_BIG 48           // split-K for the big sig GEMM (48*344 = 16512)

// ---------------------------------------------------------------------------
// Device scratch
// ---------------------------------------------------------------------------
__device__ float g_sig  [B_ * SIGDIM];      // s1 | vec(s2)
__device__ float g_M    [B_ * F_ * F_];     // M = sum_t w_t (x) w_{t+1}
__device__ float g_part [2 * NSPLIT_BIG * B_ * U_];  // big-GEMM split partials
__device__ float g_z1   [B_ * U_];
__device__ float g_yskip[B_ * U_];
__device__ float g_h2   [B_ * U_];
__device__ float g_g3   [B_ * U_];
__device__ float g_g4   [B_ * U_];
__device__ float g_attn [B_ * U_];
__device__ float g_PQ   [B_ * 1152];        // [64][128 P | 1024 Q]
__device__ float g_Wc   [1152 * U_];
__device__ float g_cur  [B_ * U_];
__device__ float g_gates[4 * B_ * U_];

struct P4 { const float* p[4]; };
struct O4 { float* p[4]; };

// ---------------------------------------------------------------------------
// Helpers
// ---------------------------------------------------------------------------
__device__ __forceinline__ float fsigmoid(float x) { return 1.0f / (1.0f + __expf(-x)); }

__device__ __forceinline__ float blockReduceSum(float v, float* smem) {
    int lane = threadIdx.x & 31, w = threadIdx.x >> 5;
    #pragma unroll
    for (int o = 16; o > 0; o >>= 1) v += __shfl_xor_sync(0xffffffffu, v, o);
    if (lane == 0) smem[w] = v;
    __syncthreads();
    int nw = blockDim.x >> 5;
    float r = (threadIdx.x < nw) ? smem[threadIdx.x] : 0.0f;
    if (w == 0) {
        #pragma unroll
        for (int o = 16; o > 0; o >>= 1) r += __shfl_xor_sync(0xffffffffu, r, o);
        if (lane == 0) smem[0] = r;
    }
    __syncthreads();
    float out = smem[0];
    __syncthreads();
    return out;
}

__device__ __forceinline__ float blockReduceMax(float v, float* smem) {
    int lane = threadIdx.x & 31, w = threadIdx.x >> 5;
    #pragma unroll
    for (int o = 16; o > 0; o >>= 1) v = fmaxf(v, __shfl_xor_sync(0xffffffffu, v, o));
    if (lane == 0) smem[w] = v;
    __syncthreads();
    int nw = blockDim.x >> 5;
    float r = (threadIdx.x < nw) ? smem[threadIdx.x] : -INFINITY;
    if (w == 0) {
        #pragma unroll
        for (int o = 16; o > 0; o >>= 1) r = fmaxf(r, __shfl_xor_sync(0xffffffffu, r, o));
        if (lane == 0) smem[0] = r;
    }
    __syncthreads();
    float out = smem[0];
    __syncthreads();
    return out;
}

// b-spline basis (grid_size=5, order=3), exact Cox-de Boor as reference
__device__ __forceinline__ void bspline8(float x, float* out) {
    float b[11];
    #pragma unroll
    for (int i = 0; i < 11; i++) {
        float gi  = -1.0f + 0.4f * (float)(i - 3);
        float gi1 = -1.0f + 0.4f * (float)(i - 2);
        b[i] = (x >= gi && x < gi1) ? 1.0f : 0.0f;
    }
    #pragma unroll
    for (int p = 1; p <= 3; p++) {
        float inv = 1.0f / (0.4f * (float)p);
        #pragma unroll
        for (int i = 0; i < 11 - p; i++) {
            float gi   = -1.0f + 0.4f * (float)(i - 3);
            float gip1 = -1.0f + 0.4f * (float)(i + p + 1 - 3);
            b[i] = (x - gi) * inv * b[i] + (gip1 - x) * inv * b[i + 1];
        }
    }
    #pragma unroll
    for (int k = 0; k < 8; k++) out[k] = b[k];
}

// ---------------------------------------------------------------------------
// K1: bias/zero init + base_w copy into Wc + s1
// ---------------------------------------------------------------------------
__global__ void init_small_kernel(const float* b2, const float* b3, const float* b4,
                                  const float* bf, const float* bi,
                                  const float* bc, const float* bo,
                                  const float* base_w,
                                  const float* __restrict__ x,
                                  const float* __restrict__ tk) {
    int idx = blockIdx.x * blockDim.x + threadIdx.x;
    const int NBIAS = 7 * B_ * U_;                 // h2,g3,g4,4 gates
    const int NCUR = B_ * U_, NPQ = B_ * 1152, NM = B_ * F_ * F_;
    const int NBASE = F_ * U_;
    if (idx < NBIAS) {
        int which = idx >> 15;
        int r = idx & 32767;
        int u = r & (U_ - 1);
        float v; float* dst;
        switch (which) {
            case 0: dst = g_h2;            v = b2[u];  break;
            case 1: dst = g_g3;            v = b3[u];  break;
            case 2: dst = g_g4;            v = b4[u];  break;
            case 3: dst = g_gates;         v = bf[u];  break;
            case 4: dst = g_gates + 32768; v = bi[u];  break;
            case 5: dst = g_gates + 65536; v = bc[u];  break;
            default: dst = g_gates + 98304; v = bo[u]; break;
        }
        dst[r] = v;
    } else {
        int r = idx - NBIAS;
        if (r < NCUR) { g_cur[r] = 0.0f; return; }
        r -= NCUR;
        if (r < NPQ) { g_PQ[r] = 0.0f; return; }
        r -= NPQ;
        if (r < NM) { g_M[r] = 0.0f; return; }
        r -= NM;
        if (r < NBASE) { g_Wc[r] = base_w[r]; return; }
        r -= NBASE;
        if (r < B_ * F_) {                 // s1 = wL - w0
            int b = r >> 7, c = r & 127;
            g_sig[b * SIGDIM + c] = tk[S_ - 1] * x[(b * S_ + S_ - 1) * F_ + c]
                                  - tk[0]      * x[b * S_ * F_ + c];
        }
    }
}

// ---------------------------------------------------------------------------
// K2: tiled transpose of spline_w (512 x 1024) into Wc rows [128..1152)
// ---------------------------------------------------------------------------
__global__ void __launch_bounds__(256) wc_spline_T(const float* __restrict__ spline_w) {
    __shared__ float tile[32][33];
    int kk0 = blockIdx.x * 32, u0 = blockIdx.y * 32;
    int tx = threadIdx.x & 31, ty = threadIdx.x >> 5;   // 32 x 8
    #pragma unroll
    for (int a = 0; a < 32; a += 8)
        tile[ty + a][tx] = spline_w[(u0 + ty + a) * 1024 + kk0 + tx];
    __syncthreads();
    #pragma unroll
    for (int a = 0; a < 32; a += 8)
        g_Wc[(F_ + kk0 + ty + a) * U_ + u0 + tx] = tile[tx][ty + a];
}

// ---------------------------------------------------------------------------
// K3: M[b,i,j] = sum_t w_t[i] * w_{t+1}[j], split-K over 4 chunks of 128 t.
// ---------------------------------------------------------------------------
__global__ void __launch_bounds__(256) sig2_kernel(const float* __restrict__ x,
                                                   const float* __restrict__ tk) {
    int b = blockIdx.y;
    int tBegin = blockIdx.x * 128;
    int tEnd = min(S_ - 1, tBegin + 128);

    __shared__ float Ws[33][128];

    int tid = threadIdx.x;
    int tx = tid & 15, ty = tid >> 4;
    const float* xb = x + b * S_ * F_;

    float acc[8][8];
    #pragma unroll
    for (int i = 0; i < 8; i++)
        #pragma unroll
        for (int j = 0; j < 8; j++) acc[i][j] = 0.0f;

    for (int t0 = tBegin; t0 < tEnd; t0 += 32) {
        int nt = min(32, tEnd - t0);
        for (int e = tid; e < (nt + 1) * 128; e += 256) {
            int kk = e >> 7, f = e & 127;
            Ws[kk][f] = tk[t0 + kk] * xb[(t0 + kk) * F_ + f];
        }
        __syncthreads();
        #pragma unroll 8
        for (int kk = 0; kk < nt; kk++) {
            float a8[8], d8[8];
            *(float4*)&a8[0] = *(const float4*)&Ws[kk][ty * 8];
            *(float4*)&a8[4] = *(const float4*)&Ws[kk][ty * 8 + 4];
            *(float4*)&d8[0] = *(const float4*)&Ws[kk + 1][tx * 8];
            *(float4*)&d8[4] = *(const float4*)&Ws[kk + 1][tx * 8 + 4];
            #pragma unroll
            for (int i = 0; i < 8; i++)
                #pragma unroll
                for (int j = 0; j < 8; j++) acc[i][j] = fmaf(a8[i], d8[j], acc[i][j]);
        }
        __syncthreads();
    }

    float* Mb = g_M + b * F_ * F_;
    #pragma unroll
    for (int i = 0; i < 8; i++)
        #pragma unroll
        for (int j = 0; j < 8; j++)
            atomicAdd(&Mb[(ty * 8 + i) * F_ + tx * 8 + j], acc[i][j]);
}

// ---------------------------------------------------------------------------
// K4: sig epilogue (tiled): s2 = 0.5(M - M^T) + 0.5 wL(x)wL + 0.5 w0(x)w0 - w0(x)wL
// grid (jTiles=4, iTiles=4, B), 256 threads, 32x32 tiles, smem transpose.
// ---------------------------------------------------------------------------
__global__ void __launch_bounds__(256) sig_epi_kernel(const float* __restrict__ x,
                                                      const float* __restrict__ tk) {
    int b = blockIdx.z;
    int i0 = blockIdx.y * 32, j0 = blockIdx.x * 32;
    __shared__ float tji[32][33];      // M[b][j0+r][i0+c]
    __shared__ float w0i_s[32], wLi_s[32], w0j_s[32], wLj_s[32];

    int tx = threadIdx.x & 31, ty = threadIdx.x >> 5;   // 32 x 8
    const float* Mb = g_M + b * F_ * F_;
    #pragma unroll
    for (int a = 0; a < 32; a += 8)
        tji[ty + a][tx] = Mb[(j0 + ty + a) * F_ + i0 + tx];
    if (threadIdx.x < 32) {
        float tk0 = tk[0], tkL = tk[S_ - 1];
        const float* xb = x + b * S_ * F_;
        w0i_s[tx] = tk0 * xb[i0 + tx];
        wLi_s[tx] = tkL * xb[(S_ - 1) * F_ + i0 + tx];
        w0j_s[tx] = tk0 * xb[j0 + tx];
        wLj_s[tx] = tkL * xb[(S_ - 1) * F_ + j0 + tx];
    }
    __syncthreads();

    float* dst = g_sig + b * SIGDIM + F_;
    float w0j = w0j_s[tx], wLj = wLj_s[tx];
    #pragma unroll
    for (int a = 0; a < 32; a += 8) {
        int i = i0 + ty + a, j = j0 + tx;
        float mij = Mb[i * F_ + j];
        float mji = tji[tx][ty + a];
        float w0i = w0i_s[ty + a], wLi = wLi_s[ty + a];
        dst[i * F_ + j] = 0.5f * (mij - mji)
                        + 0.5f * wLi * wLj + 0.5f * w0i * w0j - w0i * wLj;
    }
}

// ---------------------------------------------------------------------------
// K5: GEMM, M=64, N-tile 128, 128 threads, 8x8/thread, double-buffered smem.
// Epilogue: per-split partial store (usePart) or atomicAdd.
// ---------------------------------------------------------------------------
__global__ void __launch_bounds__(128) gemm64(
    const float* __restrict__ A, int lda, float ascale,
    const float* __restrict__ A2, int lda2, int kHalf,
    int actElu, int K, int kChunk,
    P4 Bset, int ldb, O4 Cset, int ldc,
    float* __restrict__ Cpart, int usePart)
{
    int z = blockIdx.z;
    const float* __restrict__ Bw = Bset.p[z];
    int n0 = blockIdx.x * 128;
    int kBegin = blockIdx.y * kChunk;
    int kEnd = min(K, kBegin + kChunk);

    __shared__ float As[2][16][68];
    __shared__ float Bs[2][16][128];

    int tid = threadIdx.x;
    int tx = tid & 15, ty = tid >> 4;
    int am = tid >> 2;
    int akq = (tid & 3) << 2;
    int bkk = tid >> 5;
    int bnq = (tid & 31) << 2;

    float4 aR[2], bR[4];

#define GLOAD(K0) do { \
        _Pragma("unroll") \
        for (int it = 0; it < 2; it++) { \
            int m = am + it * 32; \
            int k = (K0) + akq; \
            float4 v = make_float4(0.f, 0.f, 0.f, 0.f); \
            if (k < kEnd) { \
                if (k < kHalf) { \
                    v = *(const float4*)&A[m * lda + k]; \
                    v.x *= ascale; v.y *= ascale; v.z *= ascale; v.w *= ascale; \
                } else { \
                    v = *(const float4*)&A2[m * lda2 + (k - kHalf)]; \
                } \
            } \
            if (actElu) { \
                v.x = (v.x > 0.f) ? v.x : (__expf(v.x) - 1.f); \
                v.y = (v.y > 0.f) ? v.y : (__expf(v.y) - 1.f); \
                v.z = (v.z > 0.f) ? v.z : (__expf(v.z) - 1.f); \
                v.w = (v.w > 0.f) ? v.w : (__expf(v.w) - 1.f); \
            } \
            aR[it] = v; \
        } \
        _Pragma("unroll") \
        for (int it = 0; it < 4; it++) { \
            int k = (K0) + bkk + it * 4; \
            float4 v = make_float4(0.f, 0.f, 0.f, 0.f); \
            if (k < kEnd) v = *(const float4*)&Bw[k * ldb + n0 + bnq]; \
            bR[it] = v; \
        } \
    } while (0)

#define GSTORE(BUF) do { \
        _Pragma("unroll") \
        for (int it = 0; it < 2; it++) { \
            int m = am + it * 32; \
            As[BUF][akq + 0][m] = aR[it].x; As[BUF][akq + 1][m] = aR[it].y; \
            As[BUF][akq + 2][m] = aR[it].z; As[BUF][akq + 3][m] = aR[it].w; \
        } \
        _Pragma("unroll") \
        for (int it = 0; it < 4; it++) { \
            *(float4*)&Bs[BUF][bkk + it * 4][bnq] = bR[it]; \
        } \
    } while (0)

    float acc[8][8];
    #pragma unroll
    for (int i = 0; i < 8; i++)
        #pragma unroll
        for (int j = 0; j < 8; j++) acc[i][j] = 0.0f;

    GLOAD(kBegin);
    GSTORE(0);
    __syncthreads();

    int buf = 0;
    for (int k0 = kBegin; k0 < kEnd; k0 += 16) {
        bool nxt = (k0 + 16) < kEnd;
        if (nxt) GLOAD(k0 + 16);
        #pragma unroll
        for (int kk = 0; kk < 16; kk++) {
            float a8[8], b8[8];
            *(float4*)&a8[0] = *(const float4*)&As[buf][kk][ty * 8];
            *(float4*)&a8[4] = *(const float4*)&As[buf][kk][ty * 8 + 4];
            *(float4*)&b8[0] = *(const float4*)&Bs[buf][kk][tx * 8];
            *(float4*)&b8[4] = *(const float4*)&Bs[buf][kk][tx * 8 + 4];
            #pragma unroll
            for (int i = 0; i < 8; i++)
                #pragma unroll
                for (int j = 0; j < 8; j++) acc[i][j] = fmaf(a8[i], b8[j], acc[i][j]);
        }
        if (nxt) GSTORE(buf ^ 1);
        __syncthreads();
        buf ^= 1;
    }

    if (usePart) {
        float* dst = Cpart + ((size_t)(z * gridDim.y + blockIdx.y) * 64 + ty * 8) * ldc
                   + n0 + tx * 8;
        #pragma unroll
        for (int i = 0; i < 8; i++) {
            *(float4*)&dst[i * ldc]     = make_float4(acc[i][0], acc[i][1], acc[i][2], acc[i][3]);
            *(float4*)&dst[i * ldc + 4] = make_float4(acc[i][4], acc[i][5], acc[i][6], acc[i][7]);
        }
    } else {
        float* C = Cset.p[z];
        #pragma unroll
        for (int i = 0; i < 8; i++)
            #pragma unroll
            for (int j = 0; j < 8; j++)
                atomicAdd(&C[(ty * 8 + i) * ldc + n0 + tx * 8 + j], acc[i][j]);
    }
#undef GLOAD
#undef GSTORE
}

// ---------------------------------------------------------------------------
// K6: reduce big-GEMM partials (+bias) -> z1, yskip
// ---------------------------------------------------------------------------
__global__ void reduce_big_kernel(const float* __restrict__ b1,
                                  const float* __restrict__ bsk) {
    int idx = blockIdx.x * blockDim.x + threadIdx.x;
    if (idx >= 2 * B_ * U_) return;
    int z = idx >> 15, r = idx & 32767;
    const float* src = g_part + (size_t)z * NSPLIT_BIG * 32768 + r;
    float s = 0.0f;
    #pragma unroll
    for (int k = 0; k < NSPLIT_BIG; k++) s += src[(size_t)k * 32768];
    if (z == 0) g_z1[r]    = s + b1[r & (U_ - 1)];
    else        g_yskip[r] = s + bsk[r & (U_ - 1)];
}

// ---------------------------------------------------------------------------
// K7: fused glu + layernorm + softmax -> attn
// ---------------------------------------------------------------------------
__global__ void ln_softmax_kernel(const float* __restrict__ gamma,
                                  const float* __restrict__ beta) {
    __shared__ float red[32];
    int b = blockIdx.x, u = threadIdx.x;
    int idx = b * U_ + u;
    float v = g_yskip[idx] + fsigmoid(g_g3[idx]) * g_g4[idx];
    float mu = blockReduceSum(v, red) * (1.0f / (float)U_);
    float d = v - mu;
    float var = blockReduceSum(d * d, red) * (1.0f / (float)U_);
    float yn = d * rsqrtf(var + LN_EPS) * gamma[u] + beta[u];
    float mx = blockReduceMax(yn, red);
    float e = __expf(yn - mx);
    float s = blockReduceSum(e, red);
    g_attn[idx] = e / s;
}

// ---------------------------------------------------------------------------
// K8: P[b,f] = sum_s attn*silu(w), Q[b,f,k] = sum_s attn*bspl_k(w)
// ---------------------------------------------------------------------------
__global__ void __launch_bounds__(128) pq_kernel(const float* __restrict__ x,
                                                 const float* __restrict__ tk) {
    int b = blockIdx.x, chunk = blockIdx.y;
    int f = threadIdx.x;
    int s0 = chunk * 32;

    __shared__ float att_s[32], tk_s[32];
    if (f < 32) {
        att_s[f] = g_attn[b * U_ + s0 + f];
        tk_s[f]  = tk[s0 + f];
    }
    __syncthreads();

    float accP = 0.0f, accQ[8];
    #pragma unroll
    for (int k = 0; k < 8; k++) accQ[k] = 0.0f;

    const float* xb = x + (b * S_ + s0) * F_;
    #pragma unroll 2
    for (int si = 0; si < 32; si++) {
        float att = att_s[si];
        float xw = tk_s[si] * xb[si * F_ + f];
        float sg = fsigmoid(xw);
        accP = fmaf(att, xw * sg, accP);
        float bs[8];
        bspline8(xw, bs);
        #pragma unroll
        for (int k = 0; k < 8; k++) accQ[k] = fmaf(att, bs[k], accQ[k]);
    }
    atomicAdd(&g_PQ[b * 1152 + f], accP);
    #pragma unroll
    for (int k = 0; k < 8; k++)
        atomicAdd(&g_PQ[b * 1152 + 128 + f * 8 + k], accQ[k]);
}

// ---------------------------------------------------------------------------
// K9: LSTM elementwise -> out = [h_new | c_new]
// ---------------------------------------------------------------------------
__global__ void final_kernel(const float* __restrict__ c_prev, float* __restrict__ out) {
    int idx = blockIdx.x * blockDim.x + threadIdx.x;
    if (idx >= B_ * U_) return;
    float f = fsigmoid(g_gates[idx]);
    float i = fsigmoid(g_gates[32768 + idx]);
    float cand = tanhf(g_gates[65536 + idx]);
    float o = fsigmoid(g_gates[98304 + idx]);
    float c = f * c_prev[idx] + i * cand;
    float h = o * tanhf(c);
    out[idx] = h;
    out[B_ * U_ + idx] = c;
}

// ---------------------------------------------------------------------------
// Host launcher
// ---------------------------------------------------------------------------
extern "C" void kernel_launch(void* const* d_in, const int* in_sizes, int n_in,
                              void* d_out, int out_size) {
    const float* x        = (const float*)d_in[0];
    const float* h_prev   = (const float*)d_in[1];
    const float* c_prev   = (const float*)d_in[2];
    const float* tk       = (const float*)d_in[3];
    const float* base_w   = (const float*)d_in[4];
    const float* spline_w = (const float*)d_in[5];
    const float* w1       = (const float*)d_in[6];
    const float* b1       = (const float*)d_in[7];
    const float* w2       = (const float*)d_in[8];
    const float* b2       = (const float*)d_in[9];
    const float* w3       = (const float*)d_in[10];
    const float* b3       = (const float*)d_in[11];
    const float* w4       = (const float*)d_in[12];
    const float* b4       = (const float*)d_in[13];
    const float* ws       = (const float*)d_in[14];
    const float* bsk      = (const float*)d_in[15];
    const float* gamma    = (const float*)d_in[16];
    const float* beta     = (const float*)d_in[17];
    const float* wf       = (const float*)d_in[18];
    const float* bf       = (const float*)d_in[19];
    const float* wi       = (const float*)d_in[20];
    const float* bi       = (const float*)d_in[21];
    const float* wc       = (const float*)d_in[22];
    const float* bc       = (const float*)d_in[23];
    const float* wo       = (const float*)d_in[24];
    const float* bo       = (const float*)d_in[25];
    float* out = (float*)d_out;

    float *p_sig, *p_z1, *p_yskip, *p_h2, *p_g3, *p_g4, *p_PQ, *p_Wc, *p_cur, *p_gates, *p_part;
    cudaGetSymbolAddress((void**)&p_sig,   g_sig);
    cudaGetSymbolAddress((void**)&p_z1,    g_z1);
    cudaGetSymbolAddress((void**)&p_yskip, g_yskip);
    cudaGetSymbolAddress((void**)&p_h2,    g_h2);
    cudaGetSymbolAddress((void**)&p_g3,    g_g3);
    cudaGetSymbolAddress((void**)&p_g4,    g_g4);
    cudaGetSymbolAddress((void**)&p_PQ,    g_PQ);
    cudaGetSymbolAddress((void**)&p_Wc,    g_Wc);
    cudaGetSymbolAddress((void**)&p_cur,   g_cur);
    cudaGetSymbolAddress((void**)&p_gates, g_gates);
    cudaGetSymbolAddress((void**)&p_part,  g_part);

    const int NINIT = 7 * 32768 + 32768 + 73728 + B_ * F_ * F_ + F_ * U_ + B_ * F_;

    // (1) init: biases, zeros, base_w->Wc, s1
    init_small_kernel<<<(NINIT + 255) / 256, 256>>>(b2, b3, b4, bf, bi, bc, bo,
                                                    base_w, x, tk);
    // (2) signature level-2 GEMM-part (4 splits, atomic depth 4)
    sig2_kernel<<<dim3(4, B_), 256>>>(x, tk);
    // (3) signature epilogue (tiled transpose)
    sig_epi_kernel<<<dim3(4, 4, B_), 256>>>(x, tk);
    // (4) BIG fused sig projections -> per-split partials (no atomics)
    {
        P4 Bb; Bb.p[0] = w1; Bb.p[1] = ws; Bb.p[2] = w1; Bb.p[3] = w1;
        O4 Cb; Cb.p[0] = p_z1; Cb.p[1] = p_yskip; Cb.p[2] = p_z1; Cb.p[3] = p_z1;
        gemm64<<<dim3(4, NSPLIT_BIG, 2), 128>>>(p_sig, SIGDIM, 1.0f, p_sig, SIGDIM, SIGDIM,
                                                0, SIGDIM, 344, Bb, U_, Cb, U_, p_part, 1);
    }
    // (5) reduce partials + bias -> z1, yskip
    reduce_big_kernel<<<(2 * B_ * U_ + 255) / 256, 256>>>(b1, bsk);
    // (6) spline weight transpose (only needed before PQ@Wc)
    wc_spline_T<<<dim3(32, 16), 256>>>(spline_w);
    // (7) GRN: h2 = elu(z1)@w2 + b2   (atomic depth 8)
    {
        P4 Bb; Bb.p[0] = w2; Bb.p[1] = w2; Bb.p[2] = w2; Bb.p[3] = w2;
        O4 Cb; Cb.p[0] = p_h2; Cb.p[1] = p_h2; Cb.p[2] = p_h2; Cb.p[3] = p_h2;
        gemm64<<<dim3(4, 8, 1), 128>>>(p_z1, U_, 1.0f, p_z1, U_, U_,
                                       1, U_, 64, Bb, U_, Cb, U_, nullptr, 0);
    }
    // (8) g3, g4 fused (atomic depth 8)
    {
        P4 Bb; Bb.p[0] = w3; Bb.p[1] = w4; Bb.p[2] = w3; Bb.p[3] = w3;
        O4 Cb; Cb.p[0] = p_g3; Cb.p[1] = p_g4; Cb.p[2] = p_g3; Cb.p[3] = p_g3;
        gemm64<<<dim3(4, 8, 2), 128>>>(p_h2, U_, 1.0f, p_h2, U_, U_,
                                       0, U_, 64, Bb, U_, Cb, U_, nullptr, 0);
    }
    // (9) glu + LN + softmax
    ln_softmax_kernel<<<B_, U_>>>(gamma, beta);
    // (10) attention-weighted KAN reductions
    pq_kernel<<<dim3(B_, 16), 128>>>(x, tk);
    // (11) current = PQ @ Wc (atomic depth 8)
    {
        P4 Bb; Bb.p[0] = p_Wc; Bb.p[1] = p_Wc; Bb.p[2] = p_Wc; Bb.p[3] = p_Wc;
        O4 Cb; Cb.p[0] = p_cur; Cb.p[1] = p_cur; Cb.p[2] = p_cur; Cb.p[3] = p_cur;
        gemm64<<<dim3(4, 8, 1), 128>>>(p_PQ, 1152, 1.0f, p_PQ, 1152, 1152,
                                       0, 1152, 144, Bb, U_, Cb, U_, nullptr, 0);
    }
    // (12) LSTM gates: A = [cur/S , h_prev]; 4 gates fused (atomic depth 8)
    {
        P4 Bb; Bb.p[0] = wf; Bb.p[1] = wi; Bb.p[2] = wc; Bb.p[3] = wo;
        O4 Cb; Cb.p[0] = p_gates; Cb.p[1] = p_gates + 32768;
        Cb.p[2] = p_gates + 65536; Cb.p[3] = p_gates + 98304;
        gemm64<<<dim3(4, 8, 4), 128>>>(p_cur, U_, 1.0f / (float)S_, h_prev, U_, U_,
                                       0, 2 * U_, 128, Bb, U_, Cb, U_, nullptr, 0);
    }
    // (13) LSTM elementwise
    final_kernel<<<(B_ * U_ + 255) / 256, 256>>>(c_prev, out);
}